// round 14
// baseline (speedup 1.0000x reference)
#include <cuda_runtime.h>
#include <math.h>
#include <stdint.h>

// ============================================================================
// IJEPA_fMRI_base — R14: R13 + packed-uint2 pre-split tf32 planes (R12 fixed)
// ============================================================================

#define Dm    256
#define FFm   1024
#define SEQ   90
#define BTOT  720
#define MP    (BTOT*SEQ)
#define SIN   240
#define NH    8
#define HD    32
#define EPAD  768
#define EM    1488
#define BIGM  (1<<28)

__device__ float g_xemb[BTOT*Dm];
__device__ float g_student[BTOT*Dm];
__device__ float g_masks[SEQ*Dm];
__device__ float g_predt[2*BTOT*Dm];
__device__ float g_xlast[BTOT*Dm];
__device__ float g_x[(size_t)MP*Dm];
__device__ float g_ln[(size_t)MP*Dm];
__device__ float g_qkv[(size_t)MP*3*Dm];
__device__ float g_attn[(size_t)MP*Dm];
__device__ float g_ff[(size_t)MP*FFm];

__device__ __forceinline__ float gelu_f(float x) {
    float x3 = x * x * x;
    return 0.5f * x * (1.0f + tanhf(0.7978845608028654f * (x + 0.044715f * x3)));
}

enum { EP_NONE = 0, EP_RESID = 1, EP_GELU = 2, EP_BIAS_SPIKE = 3, EP_EMBED = 4 };

// ---------------- 3xTF32 helpers --------------------------------------------
__device__ __forceinline__ void split_tf32(float x, uint32_t& hi, uint32_t& lo) {
    asm("cvt.rna.tf32.f32 %0, %1;" : "=r"(hi) : "f"(x));
    float r = x - __uint_as_float(hi);
    asm("cvt.rna.tf32.f32 %0, %1;" : "=r"(lo) : "f"(r));
}
__device__ __forceinline__ void mma_tf32(float* c, const uint32_t* a, const uint32_t* b) {
    asm volatile("mma.sync.aligned.m16n8k8.row.col.f32.tf32.tf32.f32 "
        "{%0,%1,%2,%3}, {%4,%5,%6,%7}, {%8,%9}, {%0,%1,%2,%3};"
        : "+f"(c[0]), "+f"(c[1]), "+f"(c[2]), "+f"(c[3])
        : "r"(a[0]), "r"(a[1]), "r"(a[2]), "r"(a[3]), "r"(b[0]), "r"(b[1]));
}

// ---------------- big GEMM: 128x128 tile, 3xTF32, packed-split planes --------
// A-plane and B-plane hold uint2{tf32_hi, tf32_lo}, layout [k][col], stride 132.
#define PLA  (16 * 132)                 // uint2 entries per plane
#define TGSM (4 * PLA * 8)              // 2 planes x 2 buffers x 8B = 67584 B

template<int EPI>
__global__ __launch_bounds__(256) void gemm128_kernel(
    const float* __restrict__ A, const float* __restrict__ B, float* __restrict__ C,
    const float* __restrict__ resid, int M, int N, int K)
{
    extern __shared__ uint2 dsm2[];
    #define APL(b_) (dsm2 + (b_) * PLA)
    #define BPL(b_) (dsm2 + (2 + (b_)) * PLA)

    int tid = threadIdx.x;
    int row0 = blockIdx.y << 7, col0 = blockIdx.x << 7;
    int warp = tid >> 5, lane = tid & 31;
    int warpM = warp & 3, warpN = warp >> 2;
    int wm0 = warpM << 5, wn0 = warpN << 6;
    int lr = lane >> 2, lc = lane & 3;

    int arow = tid >> 2;
    int akc  = (tid & 3) << 2;
    int brow = tid >> 5;
    int bnc  = (tid & 31) << 2;
    const int KT = K >> 4;

    float4 ra0, ra1, rb0, rb1;
    const float4 fz = make_float4(0.f, 0.f, 0.f, 0.f);

    int gm0 = row0 + arow, gm1 = gm0 + 64;
    int gn  = col0 + bnc;
    bool am0 = gm0 < M, am1 = gm1 < M, bok = gn < N;

    #define FETCH(k0)                                                              \
        do {                                                                       \
            ra0 = am0 ? *(const float4*)(A + (size_t)gm0 * K + (k0) + akc) : fz;   \
            ra1 = am1 ? *(const float4*)(A + (size_t)gm1 * K + (k0) + akc) : fz;   \
            rb0 = bok ? *(const float4*)(B + (size_t)((k0) + brow)     * N + gn) : fz; \
            rb1 = bok ? *(const float4*)(B + (size_t)((k0) + brow + 8) * N + gn) : fz; \
        } while (0)

    // split once at staging; pack {hi,lo} per value
    #define STORE(b_)                                                              \
        do {                                                                       \
            uint32_t h_, l_;                                                       \
            const float av_[4] = { ra0.x, ra0.y, ra0.z, ra0.w };                   \
            const float aw_[4] = { ra1.x, ra1.y, ra1.z, ra1.w };                   \
            const float bv_[4] = { rb0.x, rb0.y, rb0.z, rb0.w };                   \
            const float bw_[4] = { rb1.x, rb1.y, rb1.z, rb1.w };                   \
            _Pragma("unroll")                                                      \
            for (int j_ = 0; j_ < 4; j_++) {                                       \
                split_tf32(av_[j_], h_, l_);                                       \
                APL(b_)[(akc + j_) * 132 + arow] = make_uint2(h_, l_);             \
                split_tf32(aw_[j_], h_, l_);                                       \
                APL(b_)[(akc + j_) * 132 + arow + 64] = make_uint2(h_, l_);        \
                split_tf32(bv_[j_], h_, l_);                                       \
                BPL(b_)[brow * 132 + bnc + j_] = make_uint2(h_, l_);               \
                split_tf32(bw_[j_], h_, l_);                                       \
                BPL(b_)[(brow + 8) * 132 + bnc + j_] = make_uint2(h_, l_);         \
            }                                                                      \
        } while (0)

    float acc[2][8][4];
    #pragma unroll
    for (int mi = 0; mi < 2; mi++)
        #pragma unroll
        for (int ni = 0; ni < 8; ni++)
            #pragma unroll
            for (int q = 0; q < 4; q++) acc[mi][ni][q] = 0.f;

    FETCH(0);
    STORE(0);
    __syncthreads();

    int buf = 0;
    for (int kt = 0; kt < KT; kt++) {
        if (kt + 1 < KT) FETCH((kt + 1) << 4);

        const uint2* AP = APL(buf);
        const uint2* BP = BPL(buf);

        #pragma unroll
        for (int k8 = 0; k8 < 16; k8 += 8) {
            int r0 = (k8 + lc) * 132, r1 = (k8 + 4 + lc) * 132;
            uint32_t ahi[2][4], alo[2][4];
            #pragma unroll
            for (int mi = 0; mi < 2; mi++) {
                int m = wm0 + (mi << 4) + lr;
                uint2 a0 = AP[r0 + m];
                uint2 a1 = AP[r0 + m + 8];
                uint2 a2 = AP[r1 + m];
                uint2 a3 = AP[r1 + m + 8];
                ahi[mi][0] = a0.x; alo[mi][0] = a0.y;
                ahi[mi][1] = a1.x; alo[mi][1] = a1.y;
                ahi[mi][2] = a2.x; alo[mi][2] = a2.y;
                ahi[mi][3] = a3.x; alo[mi][3] = a3.y;
            }
            #pragma unroll
            for (int ni = 0; ni < 8; ni++) {
                int n = wn0 + (ni << 3) + lr;
                uint2 b0 = BP[r0 + n];
                uint2 b1 = BP[r1 + n];
                uint32_t bh[2] = { b0.x, b1.x };
                uint32_t bl[2] = { b0.y, b1.y };
                #pragma unroll
                for (int mi = 0; mi < 2; mi++) {
                    mma_tf32(acc[mi][ni], ahi[mi], bh);
                    mma_tf32(acc[mi][ni], ahi[mi], bl);
                    mma_tf32(acc[mi][ni], alo[mi], bh);
                }
            }
        }

        if (kt + 1 < KT) {
            STORE(buf ^ 1);
            __syncthreads();
            buf ^= 1;
        }
    }
    #undef FETCH
    #undef STORE
    #undef APL
    #undef BPL

    #pragma unroll
    for (int mi = 0; mi < 2; mi++) {
        #pragma unroll
        for (int ni = 0; ni < 8; ni++) {
            int gr0 = row0 + wm0 + (mi << 4) + lr;
            int gr1 = gr0 + 8;
            int gc  = col0 + wn0 + (ni << 3) + (lc << 1);
            float v0 = acc[mi][ni][0], v1 = acc[mi][ni][1];
            float v2 = acc[mi][ni][2], v3 = acc[mi][ni][3];
            if (gr0 < M) {
                if (EPI == EP_RESID) {
                    v0 += resid[(size_t)gr0 * N + gc];
                    v1 += resid[(size_t)gr0 * N + gc + 1];
                } else if (EPI == EP_GELU) { v0 = gelu_f(v0); v1 = gelu_f(v1); }
                C[(size_t)gr0 * N + gc]     = v0;
                C[(size_t)gr0 * N + gc + 1] = v1;
            }
            if (gr1 < M) {
                if (EPI == EP_RESID) {
                    v2 += resid[(size_t)gr1 * N + gc];
                    v3 += resid[(size_t)gr1 * N + gc + 1];
                } else if (EPI == EP_GELU) { v2 = gelu_f(v2); v3 = gelu_f(v3); }
                C[(size_t)gr1 * N + gc]     = v2;
                C[(size_t)gr1 * N + gc + 1] = v3;
            }
        }
    }
}

// ---------------- small GEMM: 64x64 dual-weight (R4 verbatim) ----------------
template<int EPI>
__global__ __launch_bounds__(256) void gemm_kernel(
    const float* __restrict__ A, const float* __restrict__ B0,
    const float* __restrict__ B1, float* __restrict__ C,
    const float* __restrict__ resid, const float* __restrict__ bias,
    const float* __restrict__ pos, int M, int N, int K, int halfpad)
{
    __shared__ float As[16][64];
    __shared__ float Bs[16][64];
    int tid = threadIdx.x;
    int tx = tid & 15, ty = tid >> 4;
    int row0 = blockIdx.y << 6, col0 = blockIdx.x << 6;
    const float* B = (row0 >= halfpad) ? B1 : B0;
    float acc[4][4] = {};

    for (int k0 = 0; k0 < K; k0 += 16) {
        #pragma unroll
        for (int i = 0; i < 4; i++) {
            int idx = tid + (i << 8);
            int m = idx >> 4, kk = idx & 15;
            int gm = row0 + m;
            As[kk][m] = (gm < M) ? A[(size_t)gm * K + (k0 + kk)] : 0.f;
        }
        #pragma unroll
        for (int i = 0; i < 4; i++) {
            int idx = tid + (i << 8);
            int kk = idx >> 6, n = idx & 63;
            int gn = col0 + n;
            Bs[kk][n] = (gn < N) ? B[(size_t)(k0 + kk) * N + gn] : 0.f;
        }
        __syncthreads();
        #pragma unroll
        for (int kk = 0; kk < 16; kk++) {
            float a[4], b[4];
            #pragma unroll
            for (int i = 0; i < 4; i++) a[i] = As[kk][(ty << 2) + i];
            #pragma unroll
            for (int j = 0; j < 4; j++) b[j] = Bs[kk][(tx << 2) + j];
            #pragma unroll
            for (int i = 0; i < 4; i++)
                #pragma unroll
                for (int j = 0; j < 4; j++)
                    acc[i][j] = fmaf(a[i], b[j], acc[i][j]);
        }
        __syncthreads();
    }
    #pragma unroll
    for (int i = 0; i < 4; i++) {
        int gm = row0 + (ty << 2) + i;
        if (gm >= M) continue;
        #pragma unroll
        for (int j = 0; j < 4; j++) {
            int gn = col0 + (tx << 2) + j;
            if (gn >= N) continue;
            float v = acc[i][j];
            if (EPI == EP_RESID)           v += resid[(size_t)gm * N + gn];
            else if (EPI == EP_GELU)       v = gelu_f(v);
            else if (EPI == EP_BIAS_SPIKE) v = ((v + bias[gn]) > 1.0f) ? 1.f : 0.f;
            else if (EPI == EP_EMBED)
                v = ((v + bias[gn] + pos[(gm % SEQ) * N + gn]) > 1.0f) ? 1.f : 0.f;
            C[(size_t)gm * N + gn] = v;
        }
    }
}

template<int EPI>
static void launch_small(const float* A, const float* B0, const float* B1, float* C,
                         const float* resid, const float* bias, const float* pos,
                         int M, int N, int K, int halfpad)
{
    dim3 grid((N + 63) / 64, (M + 63) / 64);
    gemm_kernel<EPI><<<grid, 256>>>(A, B0, B1, C, resid, bias, pos, M, N, K, halfpad);
}

template<int EPI>
static void launch_big(const float* A, const float* B, float* C, const float* resid,
                       int M, int N, int K)
{
    cudaFuncSetAttribute(gemm128_kernel<EPI>,
                         cudaFuncAttributeMaxDynamicSharedMemorySize, TGSM);
    dim3 grid((N + 127) / 128, (M + 127) / 128);
    gemm128_kernel<EPI><<<grid, 256, TGSM>>>(A, B, C, resid, M, N, K);
}

// ---------------- LayerNorm (R4 verbatim) ------------------------------------
template<int SPIKE>
__global__ __launch_bounds__(256) void ln_kernel(
    const float* __restrict__ x,
    const float* __restrict__ g0, const float* __restrict__ b0,
    const float* __restrict__ g1, const float* __restrict__ b1,
    float* __restrict__ out, int halfpad)
{
    int row = blockIdx.x, t = threadIdx.x;
    const float* gamma = (row >= halfpad) ? g1 : g0;
    const float* beta  = (row >= halfpad) ? b1 : b0;
    size_t base = (size_t)row * Dm;
    float v = x[base + t];
    __shared__ float sh1[8], sh2[8];
    float s = v;
    #pragma unroll
    for (int o = 16; o; o >>= 1) s += __shfl_xor_sync(0xffffffffu, s, o);
    if ((t & 31) == 0) sh1[t >> 5] = s;
    __syncthreads();
    float tot = sh1[0] + sh1[1] + sh1[2] + sh1[3] + sh1[4] + sh1[5] + sh1[6] + sh1[7];
    float mean = tot * (1.0f / 256.0f);
    float d = v - mean;
    float sq = d * d;
    #pragma unroll
    for (int o = 16; o; o >>= 1) sq += __shfl_xor_sync(0xffffffffu, sq, o);
    if ((t & 31) == 0) sh2[t >> 5] = sq;
    __syncthreads();
    float var = (sh2[0] + sh2[1] + sh2[2] + sh2[3] + sh2[4] + sh2[5] + sh2[6] + sh2[7])
                * (1.0f / 256.0f);
    float y = d * rsqrtf(var + 1e-5f) * gamma[t] + beta[t];
    if (SPIKE) y = (y > 1.0f) ? 1.f : 0.f;
    out[base + t] = y;
}

// ---------------- attention: R13 verbatim (exact causal truncation) ----------
__global__ __launch_bounds__(256) void attention_kernel(
    const float* __restrict__ qkv, float* __restrict__ out, int causal,
    int seq_half, int pad_extra)
{
    int s = blockIdx.x, h = blockIdx.y;
    int row_base = s * SEQ + ((s >= seq_half) ? pad_extra : 0);
    __shared__ float q[SEQ][HD + 1], k[SEQ][HD + 1], v[SEQ][HD + 1];
    __shared__ float sc[8][SEQ];
    int tid = threadIdx.x;
    for (int idx = tid; idx < SEQ * HD; idx += 256) {
        int r = idx >> 5, j = idx & 31;
        const float* base = qkv + (size_t)(row_base + r) * (3 * Dm);
        q[r][j] = base[h * HD + j];
        k[r][j] = base[Dm + h * HD + j];
        v[r][j] = base[2 * Dm + h * HD + j];
    }
    __syncthreads();
    int warp = tid >> 5, lane = tid & 31;
    const float scale = 0.17677669529663687f;
    for (int r = warp; r < SEQ; r += 8) {
        int kend = causal ? (r + 1) : SEQ;
        float smax = -1e30f;
        for (int kk = lane; kk < kend; kk += 32) {
            float a = 0.f;
            #pragma unroll
            for (int j = 0; j < HD; j++) a = fmaf(q[r][j], k[kk][j], a);
            a *= scale;
            sc[warp][kk] = a;
            smax = fmaxf(smax, a);
        }
        #pragma unroll
        for (int o = 16; o; o >>= 1) smax = fmaxf(smax, __shfl_xor_sync(0xffffffffu, smax, o));
        float ssum = 0.f;
        for (int kk = lane; kk < kend; kk += 32) {
            float e = expf(sc[warp][kk] - smax);
            sc[warp][kk] = e;
            ssum += e;
        }
        #pragma unroll
        for (int o = 16; o; o >>= 1) ssum += __shfl_xor_sync(0xffffffffu, ssum, o);
        float inv = 1.0f / ssum;
        __syncwarp();
        float oacc = 0.f;
        for (int kk = 0; kk < kend; kk++) oacc = fmaf(sc[warp][kk], v[kk][lane], oacc);
        out[(size_t)(row_base + r) * Dm + h * HD + lane] = oacc * inv;
        __syncwarp();
    }
}

// ---------------- last-token attention (R5-proven, bit-exact) ----------------
__global__ __launch_bounds__(256) void attn_last_kernel(
    const float* __restrict__ qkv, float* __restrict__ out)
{
    int s = blockIdx.x, h = blockIdx.y;
    int row_base = s * SEQ;
    __shared__ float k[SEQ][HD + 1], v[SEQ][HD + 1];
    __shared__ float q89[HD];
    __shared__ float sc[SEQ];
    int tid = threadIdx.x;
    for (int idx = tid; idx < SEQ * HD; idx += 256) {
        int r = idx >> 5, j = idx & 31;
        const float* base = qkv + (size_t)(row_base + r) * (3 * Dm);
        k[r][j] = base[Dm + h * HD + j];
        v[r][j] = base[2 * Dm + h * HD + j];
    }
    if (tid < HD)
        q89[tid] = qkv[(size_t)(row_base + SEQ - 1) * (3 * Dm) + h * HD + tid];
    __syncthreads();
    if (tid >= 32) return;
    int lane = tid;
    const float scale = 0.17677669529663687f;
    float smax = -1e30f;
    for (int kk = lane; kk < SEQ; kk += 32) {
        float a = 0.f;
        #pragma unroll
        for (int j = 0; j < HD; j++) a = fmaf(q89[j], k[kk][j], a);
        a *= scale;
        sc[kk] = a;
        smax = fmaxf(smax, a);
    }
    #pragma unroll
    for (int o = 16; o; o >>= 1) smax = fmaxf(smax, __shfl_xor_sync(0xffffffffu, smax, o));
    float ssum = 0.f;
    for (int kk = lane; kk < SEQ; kk += 32) {
        float e = expf(sc[kk] - smax);
        sc[kk] = e;
        ssum += e;
    }
    #pragma unroll
    for (int o = 16; o; o >>= 1) ssum += __shfl_xor_sync(0xffffffffu, ssum, o);
    float inv = 1.0f / ssum;
    __syncwarp();
    float oacc = 0.f;
    for (int kk = 0; kk < SEQ; kk++) oacc = fmaf(sc[kk], v[kk][lane], oacc);
    out[(size_t)s * Dm + h * HD + lane] = oacc * inv;
}

// ---------------- helpers -----------------------------------------------------
__global__ __launch_bounds__(256) void copy_kernel(const float* __restrict__ src,
                                                   float* __restrict__ dst, int n)
{
    int i = blockIdx.x * 256 + threadIdx.x;
    if (i < n) dst[i] = src[i];
}
__global__ __launch_bounds__(256) void init_enc_kernel(const float* __restrict__ xemb,
                                                       float* __restrict__ dst)
{
    int row = blockIdx.x, d = threadIdx.x;
    float v;
    if (row < BTOT)       v = xemb[row * Dm + d];
    else if (row < EPAD)  v = 0.f;
    else                  v = xemb[(row - EPAD) * Dm + d];
    dst[(size_t)row * Dm + d] = v;
}
__global__ __launch_bounds__(256) void masks_kernel(const float* __restrict__ mask_token,
                                                    const float* __restrict__ pos,
                                                    float* __restrict__ out)
{
    int i = blockIdx.x * 256 + threadIdx.x;
    if (i < SEQ * Dm) {
        int d = i & 255;
        out[i] = ((mask_token[d] + pos[i]) > 1.0f) ? 1.f : 0.f;
    }
}
__global__ __launch_bounds__(256) void build_seq_kernel(const float* __restrict__ student,
                                                        const float* __restrict__ masks,
                                                        float* __restrict__ out)
{
    int p = blockIdx.x, d = threadIdx.x;
    int bt = p / SEQ, j = p % SEQ;
    int b = bt / SEQ, t = bt % SEQ;
    float v;
    if (j == SEQ - 1) v = masks[t * Dm + d];
    else {
        int src = (j < t) ? j : j + 1;
        v = student[(size_t)(b * SEQ + src) * Dm + d];
    }
    out[(size_t)p * Dm + d] = v;
}
__global__ __launch_bounds__(256) void gather_last_kernel(const float* __restrict__ x,
                                                          float* __restrict__ xlast)
{
    int bt = blockIdx.x, d = threadIdx.x;
    xlast[bt * Dm + d] = x[(size_t)(bt * SEQ + SEQ - 1) * Dm + d];
}
__global__ __launch_bounds__(256) void spike_kernel(const float* __restrict__ x,
                                                    float* __restrict__ out, int n)
{
    int i = blockIdx.x * 256 + threadIdx.x;
    if (i < n) out[i] = (x[i] > 1.0f) ? 1.f : 0.f;
}
__global__ __launch_bounds__(256) void mean_kernel(const float* __restrict__ src,
                                                   float* __restrict__ dst)
{
    int row = blockIdx.x, t = threadIdx.x;
    float v = (t < SIN) ? src[(size_t)row * SIN + t] : 0.f;
    __shared__ float sh[8];
    #pragma unroll
    for (int o = 16; o; o >>= 1) v += __shfl_xor_sync(0xffffffffu, v, o);
    if ((t & 31) == 0) sh[t >> 5] = v;
    __syncthreads();
    if (t == 0) {
        float tot = sh[0] + sh[1] + sh[2] + sh[3] + sh[4] + sh[5] + sh[6] + sh[7];
        dst[row] = tot * (1.0f / 240.0f);
    }
}

// ---------------- entry -------------------------------------------------------
extern "C" void kernel_launch(void* const* d_in, const int* in_sizes, int n_in,
                              void* d_out, int out_size)
{
    const float* x_in     = (const float*)d_in[0];
    const float* W_embed  = (const float*)d_in[1];
    const float* b_embed  = (const float*)d_in[2];
    const float* pos_emb  = (const float*)d_in[3];
    const float* mask_tok = (const float*)d_in[4];
    const float* norm_g   = (const float*)d_in[5];
    const float* norm_b   = (const float*)d_in[6];
    const float* W_dec    = (const float*)d_in[7];
    const float* b_dec    = (const float*)d_in[8];
    const float* t_qkv = (const float*)d_in[9];
    const float* t_out = (const float*)d_in[10];
    const float* t_ln1 = (const float*)d_in[11];
    const float* t_ff1 = (const float*)d_in[12];
    const float* t_ff2 = (const float*)d_in[13];
    const float* t_ln2 = (const float*)d_in[14];
    const float* s_qkv = (const float*)d_in[15];
    const float* s_out = (const float*)d_in[16];
    const float* s_ln1 = (const float*)d_in[17];
    const float* s_ff1 = (const float*)d_in[18];
    const float* s_ff2 = (const float*)d_in[19];
    const float* s_ln2 = (const float*)d_in[20];
    const float* p_qkv = (const float*)d_in[21];
    const float* p_out = (const float*)d_in[22];
    const float* p_ln1 = (const float*)d_in[23];
    const float* p_ff1 = (const float*)d_in[24];
    const float* p_ff2 = (const float*)d_in[25];
    const float* p_ln2 = (const float*)d_in[26];
    float* out = (float*)d_out;
    (void)in_sizes; (void)n_in; (void)out_size;

    void* p;
    cudaGetSymbolAddress(&p, g_xemb);    float* bxemb    = (float*)p;
    cudaGetSymbolAddress(&p, g_student); float* bstudent = (float*)p;
    cudaGetSymbolAddress(&p, g_masks);   float* bmasks   = (float*)p;
    cudaGetSymbolAddress(&p, g_predt);   float* bpredt   = (float*)p;
    cudaGetSymbolAddress(&p, g_xlast);   float* bxlast   = (float*)p;
    cudaGetSymbolAddress(&p, g_x);       float* bx       = (float*)p;
    cudaGetSymbolAddress(&p, g_ln);      float* bln      = (float*)p;
    cudaGetSymbolAddress(&p, g_qkv);     float* bqkv     = (float*)p;
    cudaGetSymbolAddress(&p, g_attn);    float* battn    = (float*)p;
    cudaGetSymbolAddress(&p, g_ff);      float* bff      = (float*)p;

    // 1. embed
    launch_small<EP_EMBED>(x_in, W_embed, W_embed, bxemb, nullptr, b_embed, pos_emb,
                           BTOT, Dm, SIN, BIGM);

    // 2+3. fused dual encoder
    init_enc_kernel<<<EM, 256>>>(bxemb, bx);
    for (int i = 0; i < 8; i++) {
        const float* tWq = t_qkv + (size_t)i * Dm * 3 * Dm;
        const float* sWq = s_qkv + (size_t)i * Dm * 3 * Dm;
        const float* tWo = t_out + (size_t)i * Dm * Dm;
        const float* sWo = s_out + (size_t)i * Dm * Dm;
        const float* t1g = t_ln1 + (size_t)i * 2 * Dm; const float* t1b = t1g + Dm;
        const float* s1g = s_ln1 + (size_t)i * 2 * Dm; const float* s1b = s1g + Dm;
        const float* tW1 = t_ff1 + (size_t)i * Dm * FFm;
        const float* sW1 = s_ff1 + (size_t)i * Dm * FFm;
        const float* tW2 = t_ff2 + (size_t)i * FFm * Dm;
        const float* sW2 = s_ff2 + (size_t)i * FFm * Dm;
        const float* t2g = t_ln2 + (size_t)i * 2 * Dm; const float* t2b = t2g + Dm;
        const float* s2g = s_ln2 + (size_t)i * 2 * Dm; const float* s2b = s2g + Dm;

        ln_kernel<0><<<EM, 256>>>(bx, t1g, t1b, s1g, s1b, bln, EPAD);
        launch_small<EP_NONE>(bln, tWq, sWq, bqkv, nullptr, nullptr, nullptr,
                              EM, 3 * Dm, Dm, EPAD);
        attention_kernel<<<dim3(16, NH), 256>>>(bqkv, battn, 0, 8, 48);
        launch_small<EP_RESID>(battn, tWo, sWo, bx, bx, nullptr, nullptr,
                               EM, Dm, Dm, EPAD);
        ln_kernel<0><<<EM, 256>>>(bx, t2g, t2b, s2g, s2b, bln, EPAD);
        launch_small<EP_GELU>(bln, tW1, sW1, bff, nullptr, nullptr, nullptr,
                              EM, FFm, Dm, EPAD);
        launch_small<EP_RESID>(bff, tW2, sW2, bx, bx, nullptr, nullptr,
                               EM, Dm, FFm, EPAD);
    }
    ln_kernel<1><<<BTOT, 256>>>(bx, norm_g, norm_b, norm_g, norm_b,
                                bpredt + (size_t)BTOT * Dm, BIGM);
    ln_kernel<1><<<BTOT, 256>>>(bx + (size_t)EPAD * Dm, norm_g, norm_b, norm_g, norm_b,
                                bstudent, BIGM);

    // 4. masks + leave-one-out assembly
    masks_kernel<<<(SEQ * Dm + 255) / 256, 256>>>(mask_tok, pos_emb, bmasks);
    build_seq_kernel<<<MP, 256>>>(bstudent, bmasks, bx);

    // 5. predictor: 3xTF32 tensor GEMMs; causal-truncated attention; layer 6 last-token
    for (int i = 0; i < 6; i++) {
        const float* Wqkv = p_qkv + (size_t)i * Dm * 3 * Dm;
        const float* Wo   = p_out + (size_t)i * Dm * Dm;
        const float* l1g  = p_ln1 + (size_t)i * 2 * Dm; const float* l1b = l1g + Dm;
        const float* W1   = p_ff1 + (size_t)i * Dm * FFm;
        const float* W2   = p_ff2 + (size_t)i * FFm * Dm;
        const float* l2g  = p_ln2 + (size_t)i * 2 * Dm; const float* l2b = l2g + Dm;

        ln_kernel<0><<<MP, 256>>>(bx, l1g, l1b, l1g, l1b, bln, BIGM);
        launch_big<EP_NONE>(bln, Wqkv, bqkv, nullptr, MP, 3 * Dm, Dm);

        if (i < 5) {
            attention_kernel<<<dim3(BTOT, NH), 256>>>(bqkv, battn, 1, BIGM, 0);
            launch_big<EP_RESID>(battn, Wo, bx, bx, MP, Dm, Dm);
            ln_kernel<0><<<MP, 256>>>(bx, l2g, l2b, l2g, l2b, bln, BIGM);
            launch_big<EP_GELU>(bln, W1, bff, nullptr, MP, FFm, Dm);
            launch_big<EP_RESID>(bff, W2, bx, bx, MP, Dm, FFm);
        } else {
            attn_last_kernel<<<dim3(BTOT, NH), 256>>>(bqkv, battn);
            gather_last_kernel<<<BTOT, 256>>>(bx, bxlast);
            launch_small<EP_RESID>(battn, Wo, Wo, bxlast, bxlast, nullptr, nullptr,
                                   BTOT, Dm, Dm, BIGM);
            ln_kernel<0><<<BTOT, 256>>>(bxlast, l2g, l2b, l2g, l2b, bln, BIGM);
            launch_small<EP_GELU>(bln, W1, W1, bff, nullptr, nullptr, nullptr,
                                  BTOT, FFm, Dm, BIGM);
            launch_small<EP_RESID>(bff, W2, W2, bxlast, bxlast, nullptr, nullptr,
                                   BTOT, Dm, FFm, BIGM);
        }
    }

    // 6. pred targets
    spike_kernel<<<(BTOT * Dm + 255) / 256, 256>>>(bxlast, bpredt, BTOT * Dm);

    // 7. fused decode + outputs
    launch_small<EP_BIAS_SPIKE>(bpredt, W_dec, W_dec, out, nullptr, b_dec, nullptr,
                                2 * BTOT, SIN, Dm, BIGM);
    copy_kernel<<<(172800 + 255) / 256, 256>>>(x_in, out + 345600, 172800);
    mean_kernel<<<BTOT, 256>>>(out,          out + 518400);
    mean_kernel<<<BTOT, 256>>>(out + 172800, out + 519120);
    mean_kernel<<<BTOT, 256>>>(out + 345600, out + 519840);
}

// round 15
// speedup vs baseline: 1.3271x; 1.3271x over previous
#include <cuda_runtime.h>
#include <math.h>
#include <stdint.h>

// ============================================================================
// IJEPA_fMRI_base — R15: R13 (proven 16.41ms) + bit-exact launch merges
// ============================================================================

#define Dm    256
#define FFm   1024
#define SEQ   90
#define BTOT  720
#define MP    (BTOT*SEQ)
#define SIN   240
#define NH    8
#define HD    32
#define EPAD  768
#define EM    1488
#define BIGM  (1<<28)

__device__ float g_xemb[BTOT*Dm];
__device__ float g_student[BTOT*Dm];
__device__ float g_predt[2*BTOT*Dm];
__device__ float g_xlast[BTOT*Dm];
__device__ float g_x[(size_t)MP*Dm];
__device__ float g_ln[(size_t)MP*Dm];
__device__ float g_qkv[(size_t)MP*3*Dm];
__device__ float g_attn[(size_t)MP*Dm];
__device__ float g_ff[(size_t)MP*FFm];

__device__ __forceinline__ float gelu_f(float x) {
    float x3 = x * x * x;
    return 0.5f * x * (1.0f + tanhf(0.7978845608028654f * (x + 0.044715f * x3)));
}

enum { EP_NONE = 0, EP_RESID = 1, EP_GELU = 2, EP_BIAS_SPIKE = 3, EP_EMBED = 4 };

// ---------------- 3xTF32 helpers (R11/R13 verbatim) --------------------------
__device__ __forceinline__ void split_tf32(float x, uint32_t& hi, uint32_t& lo) {
    asm("cvt.rna.tf32.f32 %0, %1;" : "=r"(hi) : "f"(x));
    float r = x - __uint_as_float(hi);
    asm("cvt.rna.tf32.f32 %0, %1;" : "=r"(lo) : "f"(r));
}
__device__ __forceinline__ void mma_tf32(float* c, const uint32_t* a, const uint32_t* b) {
    asm volatile("mma.sync.aligned.m16n8k8.row.col.f32.tf32.tf32.f32 "
        "{%0,%1,%2,%3}, {%4,%5,%6,%7}, {%8,%9}, {%0,%1,%2,%3};"
        : "+f"(c[0]), "+f"(c[1]), "+f"(c[2]), "+f"(c[3])
        : "r"(a[0]), "r"(a[1]), "r"(a[2]), "r"(a[3]), "r"(b[0]), "r"(b[1]));
}

// ---------------- big GEMM: 128x128 tile, 3xTF32 (R11/R13 verbatim) ----------
template<int EPI>
__global__ __launch_bounds__(256) void gemm128_kernel(
    const float* __restrict__ A, const float* __restrict__ B, float* __restrict__ C,
    const float* __restrict__ resid, int M, int N, int K)
{
    __shared__ float As[2][16][132];
    __shared__ float Bs[2][16][132];

    int tid = threadIdx.x;
    int row0 = blockIdx.y << 7, col0 = blockIdx.x << 7;
    int warp = tid >> 5, lane = tid & 31;
    int warpM = warp & 3, warpN = warp >> 2;
    int wm0 = warpM << 5, wn0 = warpN << 6;
    int lr = lane >> 2, lc = lane & 3;

    int arow = tid >> 2;
    int akc  = (tid & 3) << 2;
    int brow = tid >> 5;
    int bnc  = (tid & 31) << 2;
    const int KT = K >> 4;

    float4 ra0, ra1, rb0, rb1;
    const float4 fz = make_float4(0.f, 0.f, 0.f, 0.f);

    int gm0 = row0 + arow, gm1 = gm0 + 64;
    int gn  = col0 + bnc;
    bool am0 = gm0 < M, am1 = gm1 < M, bok = gn < N;

    #define FETCH(k0)                                                              \
        do {                                                                       \
            ra0 = am0 ? *(const float4*)(A + (size_t)gm0 * K + (k0) + akc) : fz;   \
            ra1 = am1 ? *(const float4*)(A + (size_t)gm1 * K + (k0) + akc) : fz;   \
            rb0 = bok ? *(const float4*)(B + (size_t)((k0) + brow)     * N + gn) : fz; \
            rb1 = bok ? *(const float4*)(B + (size_t)((k0) + brow + 8) * N + gn) : fz; \
        } while (0)

    #define STORE(buf_)                                                            \
        do {                                                                       \
            As[buf_][akc + 0][arow]      = ra0.x;                                  \
            As[buf_][akc + 1][arow]      = ra0.y;                                  \
            As[buf_][akc + 2][arow]      = ra0.z;                                  \
            As[buf_][akc + 3][arow]      = ra0.w;                                  \
            As[buf_][akc + 0][arow + 64] = ra1.x;                                  \
            As[buf_][akc + 1][arow + 64] = ra1.y;                                  \
            As[buf_][akc + 2][arow + 64] = ra1.z;                                  \
            As[buf_][akc + 3][arow + 64] = ra1.w;                                  \
            *(float4*)&Bs[buf_][brow][bnc]     = rb0;                              \
            *(float4*)&Bs[buf_][brow + 8][bnc] = rb1;                              \
        } while (0)

    float acc[2][8][4];
    #pragma unroll
    for (int mi = 0; mi < 2; mi++)
        #pragma unroll
        for (int ni = 0; ni < 8; ni++)
            #pragma unroll
            for (int q = 0; q < 4; q++) acc[mi][ni][q] = 0.f;

    FETCH(0);
    STORE(0);
    __syncthreads();

    int buf = 0;
    for (int kt = 0; kt < KT; kt++) {
        if (kt + 1 < KT) FETCH((kt + 1) << 4);

        #pragma unroll
        for (int k8 = 0; k8 < 16; k8 += 8) {
            uint32_t ahi[2][4], alo[2][4];
            #pragma unroll
            for (int mi = 0; mi < 2; mi++) {
                int m = wm0 + (mi << 4) + lr;
                float a0 = As[buf][k8 + lc][m];
                float a1 = As[buf][k8 + lc][m + 8];
                float a2 = As[buf][k8 + 4 + lc][m];
                float a3 = As[buf][k8 + 4 + lc][m + 8];
                split_tf32(a0, ahi[mi][0], alo[mi][0]);
                split_tf32(a1, ahi[mi][1], alo[mi][1]);
                split_tf32(a2, ahi[mi][2], alo[mi][2]);
                split_tf32(a3, ahi[mi][3], alo[mi][3]);
            }
            #pragma unroll
            for (int ni = 0; ni < 8; ni++) {
                int n = wn0 + (ni << 3) + lr;
                float b0 = Bs[buf][k8 + lc][n];
                float b1 = Bs[buf][k8 + 4 + lc][n];
                uint32_t bh[2], bl[2];
                split_tf32(b0, bh[0], bl[0]);
                split_tf32(b1, bh[1], bl[1]);
                #pragma unroll
                for (int mi = 0; mi < 2; mi++) {
                    mma_tf32(acc[mi][ni], ahi[mi], bh);
                    mma_tf32(acc[mi][ni], ahi[mi], bl);
                    mma_tf32(acc[mi][ni], alo[mi], bh);
                }
            }
        }

        if (kt + 1 < KT) {
            STORE(buf ^ 1);
            __syncthreads();
            buf ^= 1;
        }
    }
    #undef FETCH
    #undef STORE

    #pragma unroll
    for (int mi = 0; mi < 2; mi++) {
        #pragma unroll
        for (int ni = 0; ni < 8; ni++) {
            int gr0 = row0 + wm0 + (mi << 4) + lr;
            int gr1 = gr0 + 8;
            int gc  = col0 + wn0 + (ni << 3) + (lc << 1);
            float v0 = acc[mi][ni][0], v1 = acc[mi][ni][1];
            float v2 = acc[mi][ni][2], v3 = acc[mi][ni][3];
            if (gr0 < M) {
                if (EPI == EP_RESID) {
                    v0 += resid[(size_t)gr0 * N + gc];
                    v1 += resid[(size_t)gr0 * N + gc + 1];
                } else if (EPI == EP_GELU) { v0 = gelu_f(v0); v1 = gelu_f(v1); }
                C[(size_t)gr0 * N + gc]     = v0;
                C[(size_t)gr0 * N + gc + 1] = v1;
            }
            if (gr1 < M) {
                if (EPI == EP_RESID) {
                    v2 += resid[(size_t)gr1 * N + gc];
                    v3 += resid[(size_t)gr1 * N + gc + 1];
                } else if (EPI == EP_GELU) { v2 = gelu_f(v2); v3 = gelu_f(v3); }
                C[(size_t)gr1 * N + gc]     = v2;
                C[(size_t)gr1 * N + gc + 1] = v3;
            }
        }
    }
}

// ---------------- small GEMM: 64x64 dual-weight (R4 verbatim) ----------------
template<int EPI>
__global__ __launch_bounds__(256) void gemm_kernel(
    const float* __restrict__ A, const float* __restrict__ B0,
    const float* __restrict__ B1, float* __restrict__ C,
    const float* __restrict__ resid, const float* __restrict__ bias,
    const float* __restrict__ pos, int M, int N, int K, int halfpad)
{
    __shared__ float As[16][64];
    __shared__ float Bs[16][64];
    int tid = threadIdx.x;
    int tx = tid & 15, ty = tid >> 4;
    int row0 = blockIdx.y << 6, col0 = blockIdx.x << 6;
    const float* B = (row0 >= halfpad) ? B1 : B0;
    float acc[4][4] = {};

    for (int k0 = 0; k0 < K; k0 += 16) {
        #pragma unroll
        for (int i = 0; i < 4; i++) {
            int idx = tid + (i << 8);
            int m = idx >> 4, kk = idx & 15;
            int gm = row0 + m;
            As[kk][m] = (gm < M) ? A[(size_t)gm * K + (k0 + kk)] : 0.f;
        }
        #pragma unroll
        for (int i = 0; i < 4; i++) {
            int idx = tid + (i << 8);
            int kk = idx >> 6, n = idx & 63;
            int gn = col0 + n;
            Bs[kk][n] = (gn < N) ? B[(size_t)(k0 + kk) * N + gn] : 0.f;
        }
        __syncthreads();
        #pragma unroll
        for (int kk = 0; kk < 16; kk++) {
            float a[4], b[4];
            #pragma unroll
            for (int i = 0; i < 4; i++) a[i] = As[kk][(ty << 2) + i];
            #pragma unroll
            for (int j = 0; j < 4; j++) b[j] = Bs[kk][(tx << 2) + j];
            #pragma unroll
            for (int i = 0; i < 4; i++)
                #pragma unroll
                for (int j = 0; j < 4; j++)
                    acc[i][j] = fmaf(a[i], b[j], acc[i][j]);
        }
        __syncthreads();
    }
    #pragma unroll
    for (int i = 0; i < 4; i++) {
        int gm = row0 + (ty << 2) + i;
        if (gm >= M) continue;
        #pragma unroll
        for (int j = 0; j < 4; j++) {
            int gn = col0 + (tx << 2) + j;
            if (gn >= N) continue;
            float v = acc[i][j];
            if (EPI == EP_RESID)           v += resid[(size_t)gm * N + gn];
            else if (EPI == EP_GELU)       v = gelu_f(v);
            else if (EPI == EP_BIAS_SPIKE) v = ((v + bias[gn]) > 1.0f) ? 1.f : 0.f;
            else if (EPI == EP_EMBED)
                v = ((v + bias[gn] + pos[(gm % SEQ) * N + gn]) > 1.0f) ? 1.f : 0.f;
            C[(size_t)gm * N + gn] = v;
        }
    }
}

template<int EPI>
static void launch_small(const float* A, const float* B0, const float* B1, float* C,
                         const float* resid, const float* bias, const float* pos,
                         int M, int N, int K, int halfpad)
{
    dim3 grid((N + 63) / 64, (M + 63) / 64);
    gemm_kernel<EPI><<<grid, 256>>>(A, B0, B1, C, resid, bias, pos, M, N, K, halfpad);
}

template<int EPI>
static void launch_big(const float* A, const float* B, float* C, const float* resid,
                       int M, int N, int K)
{
    dim3 grid((N + 127) / 128, (M + 127) / 128);
    gemm128_kernel<EPI><<<grid, 256>>>(A, B, C, resid, M, N, K);
}

// ---------------- LayerNorm (R4 verbatim) ------------------------------------
template<int SPIKE>
__global__ __launch_bounds__(256) void ln_kernel(
    const float* __restrict__ x,
    const float* __restrict__ g0, const float* __restrict__ b0,
    const float* __restrict__ g1, const float* __restrict__ b1,
    float* __restrict__ out, int halfpad)
{
    int row = blockIdx.x, t = threadIdx.x;
    const float* gamma = (row >= halfpad) ? g1 : g0;
    const float* beta  = (row >= halfpad) ? b1 : b0;
    size_t base = (size_t)row * Dm;
    float v = x[base + t];
    __shared__ float sh1[8], sh2[8];
    float s = v;
    #pragma unroll
    for (int o = 16; o; o >>= 1) s += __shfl_xor_sync(0xffffffffu, s, o);
    if ((t & 31) == 0) sh1[t >> 5] = s;
    __syncthreads();
    float tot = sh1[0] + sh1[1] + sh1[2] + sh1[3] + sh1[4] + sh1[5] + sh1[6] + sh1[7];
    float mean = tot * (1.0f / 256.0f);
    float d = v - mean;
    float sq = d * d;
    #pragma unroll
    for (int o = 16; o; o >>= 1) sq += __shfl_xor_sync(0xffffffffu, sq, o);
    if ((t & 31) == 0) sh2[t >> 5] = sq;
    __syncthreads();
    float var = (sh2[0] + sh2[1] + sh2[2] + sh2[3] + sh2[4] + sh2[5] + sh2[6] + sh2[7])
                * (1.0f / 256.0f);
    float y = d * rsqrtf(var + 1e-5f) * gamma[t] + beta[t];
    if (SPIKE) y = (y > 1.0f) ? 1.f : 0.f;
    out[base + t] = y;
}

// final LN+spike for teacher (rows [0,720) of bx) and student (rows [EPAD,..)),
// merged into one launch; per-row arithmetic identical to ln_kernel<1>.
__global__ __launch_bounds__(256) void ln_spike2_kernel(
    const float* __restrict__ bx, const float* __restrict__ gamma,
    const float* __restrict__ beta, float* __restrict__ teacher_dst,
    float* __restrict__ student_dst)
{
    int row = blockIdx.x, t = threadIdx.x;
    const float* src;
    float* dst;
    if (row < BTOT) {
        src = bx + (size_t)row * Dm;
        dst = teacher_dst + (size_t)row * Dm;
    } else {
        int r = row - BTOT;
        src = bx + (size_t)(EPAD + r) * Dm;
        dst = student_dst + (size_t)r * Dm;
    }
    float v = src[t];
    __shared__ float sh1[8], sh2[8];
    float s = v;
    #pragma unroll
    for (int o = 16; o; o >>= 1) s += __shfl_xor_sync(0xffffffffu, s, o);
    if ((t & 31) == 0) sh1[t >> 5] = s;
    __syncthreads();
    float tot = sh1[0] + sh1[1] + sh1[2] + sh1[3] + sh1[4] + sh1[5] + sh1[6] + sh1[7];
    float mean = tot * (1.0f / 256.0f);
    float d = v - mean;
    float sq = d * d;
    #pragma unroll
    for (int o = 16; o; o >>= 1) sq += __shfl_xor_sync(0xffffffffu, sq, o);
    if ((t & 31) == 0) sh2[t >> 5] = sq;
    __syncthreads();
    float var = (sh2[0] + sh2[1] + sh2[2] + sh2[3] + sh2[4] + sh2[5] + sh2[6] + sh2[7])
                * (1.0f / 256.0f);
    float y = d * rsqrtf(var + 1e-5f) * gamma[t] + beta[t];
    dst[t] = (y > 1.0f) ? 1.f : 0.f;
}

// ---------------- attention (R13 verbatim, exact causal truncation) ----------
__global__ __launch_bounds__(256) void attention_kernel(
    const float* __restrict__ qkv, float* __restrict__ out, int causal,
    int seq_half, int pad_extra)
{
    int s = blockIdx.x, h = blockIdx.y;
    int row_base = s * SEQ + ((s >= seq_half) ? pad_extra : 0);
    __shared__ float q[SEQ][HD + 1], k[SEQ][HD + 1], v[SEQ][HD + 1];
    __shared__ float sc[8][SEQ];
    int tid = threadIdx.x;
    for (int idx = tid; idx < SEQ * HD; idx += 256) {
        int r = idx >> 5, j = idx & 31;
        const float* base = qkv + (size_t)(row_base + r) * (3 * Dm);
        q[r][j] = base[h * HD + j];
        k[r][j] = base[Dm + h * HD + j];
        v[r][j] = base[2 * Dm + h * HD + j];
    }
    __syncthreads();
    int warp = tid >> 5, lane = tid & 31;
    const float scale = 0.17677669529663687f;
    for (int r = warp; r < SEQ; r += 8) {
        int kend = causal ? (r + 1) : SEQ;
        float smax = -1e30f;
        for (int kk = lane; kk < kend; kk += 32) {
            float a = 0.f;
            #pragma unroll
            for (int j = 0; j < HD; j++) a = fmaf(q[r][j], k[kk][j], a);
            a *= scale;
            sc[warp][kk] = a;
            smax = fmaxf(smax, a);
        }
        #pragma unroll
        for (int o = 16; o; o >>= 1) smax = fmaxf(smax, __shfl_xor_sync(0xffffffffu, smax, o));
        float ssum = 0.f;
        for (int kk = lane; kk < kend; kk += 32) {
            float e = expf(sc[warp][kk] - smax);
            sc[warp][kk] = e;
            ssum += e;
        }
        #pragma unroll
        for (int o = 16; o; o >>= 1) ssum += __shfl_xor_sync(0xffffffffu, ssum, o);
        float inv = 1.0f / ssum;
        __syncwarp();
        float oacc = 0.f;
        for (int kk = 0; kk < kend; kk++) oacc = fmaf(sc[warp][kk], v[kk][lane], oacc);
        out[(size_t)(row_base + r) * Dm + h * HD + lane] = oacc * inv;
        __syncwarp();
    }
}

// ---------------- last-token attention (R5-proven, bit-exact) ----------------
__global__ __launch_bounds__(256) void attn_last_kernel(
    const float* __restrict__ qkv, float* __restrict__ out)
{
    int s = blockIdx.x, h = blockIdx.y;
    int row_base = s * SEQ;
    __shared__ float k[SEQ][HD + 1], v[SEQ][HD + 1];
    __shared__ float q89[HD];
    __shared__ float sc[SEQ];
    int tid = threadIdx.x;
    for (int idx = tid; idx < SEQ * HD; idx += 256) {
        int r = idx >> 5, j = idx & 31;
        const float* base = qkv + (size_t)(row_base + r) * (3 * Dm);
        k[r][j] = base[Dm + h * HD + j];
        v[r][j] = base[2 * Dm + h * HD + j];
    }
    if (tid < HD)
        q89[tid] = qkv[(size_t)(row_base + SEQ - 1) * (3 * Dm) + h * HD + tid];
    __syncthreads();
    if (tid >= 32) return;
    int lane = tid;
    const float scale = 0.17677669529663687f;
    float smax = -1e30f;
    for (int kk = lane; kk < SEQ; kk += 32) {
        float a = 0.f;
        #pragma unroll
        for (int j = 0; j < HD; j++) a = fmaf(q89[j], k[kk][j], a);
        a *= scale;
        sc[kk] = a;
        smax = fmaxf(smax, a);
    }
    #pragma unroll
    for (int o = 16; o; o >>= 1) smax = fmaxf(smax, __shfl_xor_sync(0xffffffffu, smax, o));
    float ssum = 0.f;
    for (int kk = lane; kk < SEQ; kk += 32) {
        float e = expf(sc[kk] - smax);
        sc[kk] = e;
        ssum += e;
    }
    #pragma unroll
    for (int o = 16; o; o >>= 1) ssum += __shfl_xor_sync(0xffffffffu, ssum, o);
    float inv = 1.0f / ssum;
    __syncwarp();
    float oacc = 0.f;
    for (int kk = 0; kk < SEQ; kk++) oacc = fmaf(sc[kk], v[kk][lane], oacc);
    out[(size_t)s * Dm + h * HD + lane] = oacc * inv;
}

// ---------------- helpers -----------------------------------------------------
__global__ __launch_bounds__(256) void copy_kernel(const float* __restrict__ src,
                                                   float* __restrict__ dst, int n)
{
    int i = blockIdx.x * 256 + threadIdx.x;
    if (i < n) dst[i] = src[i];
}
__global__ __launch_bounds__(256) void init_enc_kernel(const float* __restrict__ xemb,
                                                       float* __restrict__ dst)
{
    int row = blockIdx.x, d = threadIdx.x;
    float v;
    if (row < BTOT)       v = xemb[row * Dm + d];
    else if (row < EPAD)  v = 0.f;
    else                  v = xemb[(row - EPAD) * Dm + d];
    dst[(size_t)row * Dm + d] = v;
}
// leave-one-out assembly with inline mask spike (same expression as before)
__global__ __launch_bounds__(256) void build_seq_kernel(const float* __restrict__ student,
                                                        const float* __restrict__ mask_token,
                                                        const float* __restrict__ pos,
                                                        float* __restrict__ out)
{
    int p = blockIdx.x, d = threadIdx.x;
    int bt = p / SEQ, j = p % SEQ;
    int b = bt / SEQ, t = bt % SEQ;
    float v;
    if (j == SEQ - 1) {
        v = ((mask_token[d] + pos[t * Dm + d]) > 1.0f) ? 1.f : 0.f;
    } else {
        int src = (j < t) ? j : j + 1;
        v = student[(size_t)(b * SEQ + src) * Dm + d];
    }
    out[(size_t)p * Dm + d] = v;
}
__global__ __launch_bounds__(256) void gather_last_kernel(const float* __restrict__ x,
                                                          float* __restrict__ xlast)
{
    int bt = blockIdx.x, d = threadIdx.x;
    xlast[bt * Dm + d] = x[(size_t)(bt * SEQ + SEQ - 1) * Dm + d];
}
__global__ __launch_bounds__(256) void spike_kernel(const float* __restrict__ x,
                                                    float* __restrict__ out, int n)
{
    int i = blockIdx.x * 256 + threadIdx.x;
    if (i < n) out[i] = (x[i] > 1.0f) ? 1.f : 0.f;
}
// three means in one launch: which = blockIdx.x / BTOT selects the section
__global__ __launch_bounds__(256) void mean3_kernel(const float* __restrict__ base,
                                                    float* __restrict__ dst)
{
    int which = blockIdx.x / BTOT;
    int row = blockIdx.x % BTOT;
    int t = threadIdx.x;
    const float* src = base + (size_t)which * 172800;
    float v = (t < SIN) ? src[(size_t)row * SIN + t] : 0.f;
    __shared__ float sh[8];
    #pragma unroll
    for (int o = 16; o; o >>= 1) v += __shfl_xor_sync(0xffffffffu, v, o);
    if ((t & 31) == 0) sh[t >> 5] = v;
    __syncthreads();
    if (t == 0) {
        float tot = sh[0] + sh[1] + sh[2] + sh[3] + sh[4] + sh[5] + sh[6] + sh[7];
        dst[which * BTOT + row] = tot * (1.0f / 240.0f);
    }
}

// ---------------- entry -------------------------------------------------------
extern "C" void kernel_launch(void* const* d_in, const int* in_sizes, int n_in,
                              void* d_out, int out_size)
{
    const float* x_in     = (const float*)d_in[0];
    const float* W_embed  = (const float*)d_in[1];
    const float* b_embed  = (const float*)d_in[2];
    const float* pos_emb  = (const float*)d_in[3];
    const float* mask_tok = (const float*)d_in[4];
    const float* norm_g   = (const float*)d_in[5];
    const float* norm_b   = (const float*)d_in[6];
    const float* W_dec    = (const float*)d_in[7];
    const float* b_dec    = (const float*)d_in[8];
    const float* t_qkv = (const float*)d_in[9];
    const float* t_out = (const float*)d_in[10];
    const float* t_ln1 = (const float*)d_in[11];
    const float* t_ff1 = (const float*)d_in[12];
    const float* t_ff2 = (const float*)d_in[13];
    const float* t_ln2 = (const float*)d_in[14];
    const float* s_qkv = (const float*)d_in[15];
    const float* s_out = (const float*)d_in[16];
    const float* s_ln1 = (const float*)d_in[17];
    const float* s_ff1 = (const float*)d_in[18];
    const float* s_ff2 = (const float*)d_in[19];
    const float* s_ln2 = (const float*)d_in[20];
    const float* p_qkv = (const float*)d_in[21];
    const float* p_out = (const float*)d_in[22];
    const float* p_ln1 = (const float*)d_in[23];
    const float* p_ff1 = (const float*)d_in[24];
    const float* p_ff2 = (const float*)d_in[25];
    const float* p_ln2 = (const float*)d_in[26];
    float* out = (float*)d_out;
    (void)in_sizes; (void)n_in; (void)out_size;

    void* p;
    cudaGetSymbolAddress(&p, g_xemb);    float* bxemb    = (float*)p;
    cudaGetSymbolAddress(&p, g_student); float* bstudent = (float*)p;
    cudaGetSymbolAddress(&p, g_predt);   float* bpredt   = (float*)p;
    cudaGetSymbolAddress(&p, g_xlast);   float* bxlast   = (float*)p;
    cudaGetSymbolAddress(&p, g_x);       float* bx       = (float*)p;
    cudaGetSymbolAddress(&p, g_ln);      float* bln      = (float*)p;
    cudaGetSymbolAddress(&p, g_qkv);     float* bqkv     = (float*)p;
    cudaGetSymbolAddress(&p, g_attn);    float* battn    = (float*)p;
    cudaGetSymbolAddress(&p, g_ff);      float* bff      = (float*)p;

    // 1. embed
    launch_small<EP_EMBED>(x_in, W_embed, W_embed, bxemb, nullptr, b_embed, pos_emb,
                           BTOT, Dm, SIN, BIGM);

    // 2+3. fused dual encoder
    init_enc_kernel<<<EM, 256>>>(bxemb, bx);
    for (int i = 0; i < 8; i++) {
        const float* tWq = t_qkv + (size_t)i * Dm * 3 * Dm;
        const float* sWq = s_qkv + (size_t)i * Dm * 3 * Dm;
        const float* tWo = t_out + (size_t)i * Dm * Dm;
        const float* sWo = s_out + (size_t)i * Dm * Dm;
        const float* t1g = t_ln1 + (size_t)i * 2 * Dm; const float* t1b = t1g + Dm;
        const float* s1g = s_ln1 + (size_t)i * 2 * Dm; const float* s1b = s1g + Dm;
        const float* tW1 = t_ff1 + (size_t)i * Dm * FFm;
        const float* sW1 = s_ff1 + (size_t)i * Dm * FFm;
        const float* tW2 = t_ff2 + (size_t)i * FFm * Dm;
        const float* sW2 = s_ff2 + (size_t)i * FFm * Dm;
        const float* t2g = t_ln2 + (size_t)i * 2 * Dm; const float* t2b = t2g + Dm;
        const float* s2g = s_ln2 + (size_t)i * 2 * Dm; const float* s2b = s2g + Dm;

        ln_kernel<0><<<EM, 256>>>(bx, t1g, t1b, s1g, s1b, bln, EPAD);
        launch_small<EP_NONE>(bln, tWq, sWq, bqkv, nullptr, nullptr, nullptr,
                              EM, 3 * Dm, Dm, EPAD);
        attention_kernel<<<dim3(16, NH), 256>>>(bqkv, battn, 0, 8, 48);
        launch_small<EP_RESID>(battn, tWo, sWo, bx, bx, nullptr, nullptr,
                               EM, Dm, Dm, EPAD);
        ln_kernel<0><<<EM, 256>>>(bx, t2g, t2b, s2g, s2b, bln, EPAD);
        launch_small<EP_GELU>(bln, tW1, sW1, bff, nullptr, nullptr, nullptr,
                              EM, FFm, Dm, EPAD);
        launch_small<EP_RESID>(bff, tW2, sW2, bx, bx, nullptr, nullptr,
                               EM, Dm, FFm, EPAD);
    }
    // teacher spikes -> rows [720,1440) of predt; student spikes -> bstudent
    ln_spike2_kernel<<<2 * BTOT, 256>>>(bx, norm_g, norm_b,
                                        bpredt + (size_t)BTOT * Dm, bstudent);

    // 4. leave-one-out assembly (masks inlined)
    build_seq_kernel<<<MP, 256>>>(bstudent, mask_tok, pos_emb, bx);

    // 5. predictor: 3xTF32 tensor GEMMs; causal-truncated attention; layer 6 last-token
    for (int i = 0; i < 6; i++) {
        const float* Wqkv = p_qkv + (size_t)i * Dm * 3 * Dm;
        const float* Wo   = p_out + (size_t)i * Dm * Dm;
        const float* l1g  = p_ln1 + (size_t)i * 2 * Dm; const float* l1b = l1g + Dm;
        const float* W1   = p_ff1 + (size_t)i * Dm * FFm;
        const float* W2   = p_ff2 + (size_t)i * FFm * Dm;
        const float* l2g  = p_ln2 + (size_t)i * 2 * Dm; const float* l2b = l2g + Dm;

        ln_kernel<0><<<MP, 256>>>(bx, l1g, l1b, l1g, l1b, bln, BIGM);
        launch_big<EP_NONE>(bln, Wqkv, bqkv, nullptr, MP, 3 * Dm, Dm);

        if (i < 5) {
            attention_kernel<<<dim3(BTOT, NH), 256>>>(bqkv, battn, 1, BIGM, 0);
            launch_big<EP_RESID>(battn, Wo, bx, bx, MP, Dm, Dm);
            ln_kernel<0><<<MP, 256>>>(bx, l2g, l2b, l2g, l2b, bln, BIGM);
            launch_big<EP_GELU>(bln, W1, bff, nullptr, MP, FFm, Dm);
            launch_big<EP_RESID>(bff, W2, bx, bx, MP, Dm, FFm);
        } else {
            attn_last_kernel<<<dim3(BTOT, NH), 256>>>(bqkv, battn);
            gather_last_kernel<<<BTOT, 256>>>(bx, bxlast);
            launch_small<EP_RESID>(battn, Wo, Wo, bxlast, bxlast, nullptr, nullptr,
                                   BTOT, Dm, Dm, BIGM);
            ln_kernel<0><<<BTOT, 256>>>(bxlast, l2g, l2b, l2g, l2b, bln, BIGM);
            launch_small<EP_GELU>(bln, W1, W1, bff, nullptr, nullptr, nullptr,
                                  BTOT, FFm, Dm, BIGM);
            launch_small<EP_RESID>(bff, W2, W2, bxlast, bxlast, nullptr, nullptr,
                                   BTOT, Dm, FFm, BIGM);
        }
    }

    // 6. pred targets
    spike_kernel<<<(BTOT * Dm + 255) / 256, 256>>>(bxlast, bpredt, BTOT * Dm);

    // 7. fused decode + outputs
    launch_small<EP_BIAS_SPIKE>(bpredt, W_dec, W_dec, out, nullptr, b_dec, nullptr,
                                2 * BTOT, SIN, Dm, BIGM);
    copy_kernel<<<(172800 + 255) / 256, 256>>>(x_in, out + 345600, 172800);
    mean3_kernel<<<3 * BTOT, 256>>>(out, out + 518400);
}